// round 2
// baseline (speedup 1.0000x reference)
#include <cuda_runtime.h>
#include <math.h>

// Fixed problem shapes
#define HH 128
#define WW 128
#define NPIX 16384          // H*W
#define CDIM 128
#define NB 2
#define NV 6
#define BVI 12              // B*V

typedef unsigned long long u64;

// ---------------- scratch (device globals; no allocs) ----------------
__device__ float g_bufA[(size_t)BVI * CDIM * NPIX];
__device__ float g_bufB[(size_t)BVI * CDIM * NPIX];
__device__ float g_bufC[(size_t)BVI * CDIM * NPIX];
__device__ float g_hg  [(size_t)BVI * 2 * CDIM * NPIX];
__device__ float g_alp [(size_t)BVI * NPIX];
__device__ float g_pool[(size_t)NB * CDIM * NPIX];
__device__ float g_u   [(size_t)NB * CDIM * NPIX];

__device__ __forceinline__ float gelu_exact(float x) {
    return 0.5f * x * (1.0f + erff(x * 0.70710678118654752f));
}

// ---------------- packed f32x2 helpers ----------------
__device__ __forceinline__ u64 pack2(float lo, float hi) {
    u64 r; asm("mov.b64 %0, {%1, %2};" : "=l"(r) : "f"(lo), "f"(hi)); return r;
}
__device__ __forceinline__ void unpack2(u64 v, float &lo, float &hi) {
    asm("mov.b64 {%0, %1}, %2;" : "=f"(lo), "=f"(hi) : "l"(v));
}
__device__ __forceinline__ void ffma2(u64 &d, u64 a, u64 b) {
    asm("fma.rn.f32x2 %0, %1, %2, %0;" : "+l"(d) : "l"(a), "l"(b));
}

// ---------------- generic 1x1-conv GEMM with packed FFMA2 ----------------
// Out[m,p] = W[m,:]@X[:,p]; X layout per-image channel-major.
// EPI: 0 = (+bias if given); 1 = gelu(+bias); 2 = +bias + residual
constexpr int BM = 128, BN = 128, BK = 8, TM = 8, TN = 8;

template <int KTOT, int MTOT, int EPI, bool SPLIT>
__global__ __launch_bounds__(256) void gemm1x1(
    const float* __restrict__ X0, const float* __restrict__ X1,
    const float* __restrict__ W,  const float* __restrict__ Bias,
    const float* __restrict__ Res, float* __restrict__ Out)
{
    __shared__ u64   As2[BK][BM];   // W value duplicated into both halves
    __shared__ float Bs [BK][BN];

    const int img = blockIdx.z;
    const int p0  = blockIdx.x * BN;
    const int m0  = blockIdx.y * BM;
    const int tid = threadIdx.x;
    const int tx  = tid & 15;
    const int ty  = tid >> 4;

    u64 acc[TM][TN / 2];
#pragma unroll
    for (int i = 0; i < TM; i++)
#pragma unroll
        for (int j = 0; j < TN / 2; j++) acc[i][j] = 0ull;

    for (int k0 = 0; k0 < KTOT; k0 += BK) {
        // A tile: W[m0..m0+127][k0..k0+7], packed (w,w)
#pragma unroll
        for (int l = 0; l < 4; l++) {
            int i = tid + l * 256;
            int m = i >> 3, k = i & 7;
            float w = W[(size_t)(m0 + m) * KTOT + k0 + k];
            As2[k][m] = pack2(w, w);
        }
        // B tile: X[k0..k0+7][p0..p0+127]
#pragma unroll
        for (int l = 0; l < 4; l++) {
            int i = tid + l * 256;
            int k = i >> 7, n = i & 127;
            int kk = k0 + k;
            float v;
            if (SPLIT) {
                if (kk < CDIM) v = X0[((size_t)img * CDIM + kk) * NPIX + p0 + n];
                else           v = X1[((size_t)img * CDIM + (kk - CDIM)) * NPIX + p0 + n];
            } else {
                v = X0[((size_t)img * KTOT + kk) * NPIX + p0 + n];
            }
            Bs[k][n] = v;
        }
        __syncthreads();

#pragma unroll
        for (int k = 0; k < BK; k++) {
            u64 a2[TM];
            const ulonglong2* ap = reinterpret_cast<const ulonglong2*>(&As2[k][ty * TM]);
            ulonglong2 t0 = ap[0], t1 = ap[1], t2 = ap[2], t3 = ap[3];
            a2[0] = t0.x; a2[1] = t0.y; a2[2] = t1.x; a2[3] = t1.y;
            a2[4] = t2.x; a2[5] = t2.y; a2[6] = t3.x; a2[7] = t3.y;
            const ulonglong2* bp = reinterpret_cast<const ulonglong2*>(&Bs[k][tx * TN]);
            ulonglong2 u0 = bp[0], u1 = bp[1];
            u64 b2[TN / 2] = {u0.x, u0.y, u1.x, u1.y};
#pragma unroll
            for (int i = 0; i < TM; i++)
#pragma unroll
                for (int j = 0; j < TN / 2; j++)
                    ffma2(acc[i][j], a2[i], b2[j]);
        }
        __syncthreads();
    }

#pragma unroll
    for (int i = 0; i < TM; i++) {
        int m = m0 + ty * TM + i;
        float bias = Bias ? Bias[m] : 0.f;
        size_t obase = ((size_t)img * MTOT + m) * NPIX + p0 + tx * TN;
        float v[TN];
#pragma unroll
        for (int j = 0; j < TN / 2; j++) unpack2(acc[i][j], v[2 * j], v[2 * j + 1]);
#pragma unroll
        for (int j = 0; j < TN; j++) {
            float x = v[j] + bias;
            if (EPI == 1) x = gelu_exact(x);
            if (EPI == 2) x += Res[((size_t)img * CDIM + m) * NPIX + p0 + tx * TN + j];
            v[j] = x;
        }
        *reinterpret_cast<float4*>(&Out[obase])     = make_float4(v[0], v[1], v[2], v[3]);
        *reinterpret_cast<float4*>(&Out[obase + 4]) = make_float4(v[4], v[5], v[6], v[7]);
    }
}

// ---------------- depthwise 3x3 + bias + GELU ----------------
__global__ __launch_bounds__(256) void dw3x3(
    const float* __restrict__ in, const float* __restrict__ wd,
    const float* __restrict__ bd, float* __restrict__ out)
{
    int c = blockIdx.y, img = blockIdx.z;
    int pix = blockIdx.x * 256 + threadIdx.x;
    int h = pix >> 7, w = pix & 127;
    const float* p = in + ((size_t)img * CDIM + c) * NPIX;
    float s = bd[c];
#pragma unroll
    for (int ky = 0; ky < 3; ky++) {
        int hh = h + ky - 1;
        if ((unsigned)hh >= 128u) continue;
#pragma unroll
        for (int kx = 0; kx < 3; kx++) {
            int ww = w + kx - 1;
            if ((unsigned)ww >= 128u) continue;
            s = fmaf(wd[c * 9 + ky * 3 + kx], p[hh * WW + ww], s);
        }
    }
    out[((size_t)img * CDIM + c) * NPIX + pix] = gelu_exact(s);
}

// ---------------- minGRU scan over V (both passes forward: H-flips cancel) ----------------
__global__ __launch_bounds__(256) void gru_scan(const float* __restrict__ hg, float* __restrict__ g)
{
    int c = blockIdx.y, b = blockIdx.z;
    int pix = blockIdx.x * 256 + threadIdx.x;
    float h = 0.f;
#pragma unroll
    for (int v = 0; v < NV; v++) {
        size_t base = (((size_t)(b * NV + v)) * 2 * CDIM + c) * NPIX + pix;
        float hid = hg[base];
        float gt  = hg[base + (size_t)CDIM * NPIX];
        float z  = 1.f / (1.f + expf(-gt));
        float ht = (hid >= 0.f) ? (hid + 0.5f) : (1.f / (1.f + expf(-hid)));
        h = (1.f - z) * h + z * ht;
        g[(((size_t)(b * NV + v)) * CDIM + c) * NPIX + pix] = h;
    }
}

// ---------------- alpha: 3x3 conv C->1 ----------------
__global__ __launch_bounds__(256) void alpha_conv(
    const float* __restrict__ g2, const float* __restrict__ aw,
    const float* __restrict__ ab, float* __restrict__ alpha)
{
    __shared__ float w[1152];
    for (int i = threadIdx.x; i < 1152; i += 256) w[i] = aw[i];
    __syncthreads();
    int img = blockIdx.z;
    int pix = blockIdx.x * 256 + threadIdx.x;
    int h = pix >> 7, x = pix & 127;
    float s = ab[0];
    const float* base = g2 + (size_t)img * CDIM * NPIX;
    for (int c = 0; c < CDIM; c++) {
        const float* p  = base + (size_t)c * NPIX;
        const float* wc = w + c * 9;
#pragma unroll
        for (int ky = 0; ky < 3; ky++) {
            int hh = h + ky - 1;
            if ((unsigned)hh >= 128u) continue;
#pragma unroll
            for (int kx = 0; kx < 3; kx++) {
                int ww = x + kx - 1;
                if ((unsigned)ww >= 128u) continue;
                s = fmaf(wc[ky * 3 + kx], p[hh * WW + ww], s);
            }
        }
    }
    alpha[(size_t)img * NPIX + pix] = s;
}

// ---------------- softmax over V + weighted pool ----------------
__global__ __launch_bounds__(256) void pool_k(
    const float* __restrict__ g2, const float* __restrict__ alpha, float* __restrict__ out)
{
    int b = blockIdx.z;
    int pix = blockIdx.x * 256 + threadIdx.x;
    float a[NV];
    float mx = -1e30f;
#pragma unroll
    for (int v = 0; v < NV; v++) {
        a[v] = alpha[(size_t)(b * NV + v) * NPIX + pix];
        mx = fmaxf(mx, a[v]);
    }
    float sum = 0.f;
#pragma unroll
    for (int v = 0; v < NV; v++) { a[v] = expf(a[v] - mx); sum += a[v]; }
    float inv = 1.f / sum;
#pragma unroll
    for (int v = 0; v < NV; v++) a[v] *= inv;
    for (int c = 0; c < CDIM; c++) {
        float s = 0.f;
#pragma unroll
        for (int v = 0; v < NV; v++)
            s = fmaf(a[v], g2[(((size_t)(b * NV + v)) * CDIM + c) * NPIX + pix], s);
        out[((size_t)b * CDIM + c) * NPIX + pix] = s;
    }
}

// ---------------- pixel-shuffle(4) + 3x3 conv 8->3 (512->512 resize = identity) ----------------
__global__ __launch_bounds__(256) void outc_k(
    const float* __restrict__ u, const float* __restrict__ wt,
    const float* __restrict__ bs, float* __restrict__ out)
{
    __shared__ float w[216];
    if (threadIdx.x < 216) w[threadIdx.x] = wt[threadIdx.x];
    __syncthreads();
    int b = blockIdx.z, co = blockIdx.y;
    int idx = blockIdx.x * 256 + threadIdx.x;
    int y = idx >> 9, x = idx & 511;
    float s = bs[co];
    const float* ub = u + (size_t)b * CDIM * NPIX;
#pragma unroll
    for (int ky = 0; ky < 3; ky++) {
        int yy = y + ky - 1;
        if ((unsigned)yy >= 512u) continue;
        int sy = yy & 3, hy = yy >> 2;
#pragma unroll
        for (int kx = 0; kx < 3; kx++) {
            int xx = x + kx - 1;
            if ((unsigned)xx >= 512u) continue;
            int sx = xx & 3, hx = xx >> 2;
            const float* up = ub + (size_t)(sy * 4 + sx) * NPIX + hy * WW + hx;
#pragma unroll
            for (int ci = 0; ci < 8; ci++)
                s = fmaf(w[(co * 8 + ci) * 9 + ky * 3 + kx], up[(size_t)ci * 16 * NPIX], s);
        }
    }
    out[((size_t)b * 3 + co) * (512 * 512) + idx] = s;
}

// ---------------- launch ----------------
extern "C" void kernel_launch(void* const* d_in, const int* in_sizes, int n_in,
                              void* d_out, int out_size)
{
    const float* feats     = (const float*)d_in[0];
    const float* prj       = (const float*)d_in[1];
    const float* merge_w1  = (const float*)d_in[2];
    const float* merge_b1  = (const float*)d_in[3];
    const float* merge_wd  = (const float*)d_in[4];
    const float* merge_bd  = (const float*)d_in[5];
    const float* merge_w2  = (const float*)d_in[6];
    const float* merge_b2  = (const float*)d_in[7];
    const float* gru_w     = (const float*)d_in[8];
    const float* gru_bw    = (const float*)d_in[9];
    const float* alpha_w   = (const float*)d_in[10];
    const float* alpha_b   = (const float*)d_in[11];
    const float* up_w      = (const float*)d_in[12];
    const float* up_b      = (const float*)d_in[13];
    const float* outc_w    = (const float*)d_in[14];
    const float* outc_b    = (const float*)d_in[15];

    float *bufA, *bufB, *bufC, *hg, *alp, *pool, *u;
    cudaGetSymbolAddress((void**)&bufA, g_bufA);
    cudaGetSymbolAddress((void**)&bufB, g_bufB);
    cudaGetSymbolAddress((void**)&bufC, g_bufC);
    cudaGetSymbolAddress((void**)&hg,   g_hg);
    cudaGetSymbolAddress((void**)&alp,  g_alp);
    cudaGetSymbolAddress((void**)&pool, g_pool);
    cudaGetSymbolAddress((void**)&u,    g_u);

    gemm1x1<256, 128, 1, true ><<<dim3(128, 1, BVI), 256>>>(feats, prj, merge_w1, merge_b1, nullptr, bufA);
    dw3x3<<<dim3(64, CDIM, BVI), 256>>>(bufA, merge_wd, merge_bd, bufB);
    gemm1x1<128, 128, 2, false><<<dim3(128, 1, BVI), 256>>>(bufB, nullptr, merge_w2, merge_b2, feats, bufC);
    gemm1x1<128, 256, 0, false><<<dim3(128, 2, BVI), 256>>>(bufC, nullptr, gru_w, nullptr, nullptr, hg);
    gru_scan<<<dim3(64, CDIM, NB), 256>>>(hg, bufA);
    gemm1x1<128, 256, 0, false><<<dim3(128, 2, BVI), 256>>>(bufA, nullptr, gru_bw, nullptr, nullptr, hg);
    gru_scan<<<dim3(64, CDIM, NB), 256>>>(hg, bufB);
    alpha_conv<<<dim3(64, 1, BVI), 256>>>(bufB, alpha_w, alpha_b, alp);
    pool_k<<<dim3(64, 1, NB), 256>>>(bufB, alp, pool);
    gemm1x1<128, 128, 0, false><<<dim3(128, 1, NB), 256>>>(pool, nullptr, up_w, up_b, nullptr, u);
    outc_k<<<dim3(1024, 3, NB), 256>>>(u, outc_w, outc_b, (float*)d_out);
}

// round 4
// speedup vs baseline: 1.8043x; 1.8043x over previous
#include <cuda_runtime.h>
#include <cuda_bf16.h>
#include <math.h>
#include <stdint.h>

#define HH 128
#define WW 128
#define NPIX 16384
#define CDIM 128
#define NB 2
#define NV 6
#define BVI 12

// ---------------- scratch ----------------
__device__ float g_bufA[(size_t)BVI * CDIM * NPIX];
__device__ float g_bufB[(size_t)BVI * CDIM * NPIX];
__device__ float g_bufC[(size_t)BVI * CDIM * NPIX];
__device__ float g_hg  [(size_t)BVI * 2 * CDIM * NPIX];
__device__ float g_alp [(size_t)BVI * NPIX];
__device__ float g_pool[(size_t)NB * CDIM * NPIX];
__device__ float g_u   [(size_t)NB * CDIM * NPIX];

__device__ __forceinline__ float gelu_exact(float x) {
    return 0.5f * x * (1.0f + erff(x * 0.70710678118654752f));
}

__device__ __forceinline__ uint32_t smem_u32(const void* p) {
    return (uint32_t)__cvta_generic_to_shared(p);
}

// fp32 pair -> bf16x2 hi + bf16x2 lo(residual); lo halfword = first element
__device__ __forceinline__ void split_pack(float v0, float v1, uint32_t& hi, uint32_t& lo) {
    asm("cvt.rn.bf16x2.f32 %0, %1, %2;" : "=r"(hi) : "f"(v1), "f"(v0));
    float r0 = v0 - __uint_as_float(hi << 16);
    float r1 = v1 - __uint_as_float(hi & 0xffff0000u);
    asm("cvt.rn.bf16x2.f32 %0, %1, %2;" : "=r"(lo) : "f"(r1), "f"(r0));
}

__device__ __forceinline__ void ldm_x4(uint32_t* r, uint32_t addr) {
    asm volatile("ldmatrix.sync.aligned.m8n8.x4.shared.b16 {%0,%1,%2,%3}, [%4];"
                 : "=r"(r[0]), "=r"(r[1]), "=r"(r[2]), "=r"(r[3]) : "r"(addr));
}
__device__ __forceinline__ void ldm_x4t(uint32_t* r, uint32_t addr) {
    asm volatile("ldmatrix.sync.aligned.m8n8.x4.trans.shared.b16 {%0,%1,%2,%3}, [%4];"
                 : "=r"(r[0]), "=r"(r[1]), "=r"(r[2]), "=r"(r[3]) : "r"(addr));
}
__device__ __forceinline__ void mma_bf16(float* d, const uint32_t* a, const uint32_t* b) {
    asm volatile(
        "mma.sync.aligned.m16n8k16.row.col.f32.bf16.bf16.f32 "
        "{%0,%1,%2,%3}, {%4,%5,%6,%7}, {%8,%9}, {%0,%1,%2,%3};"
        : "+f"(d[0]), "+f"(d[1]), "+f"(d[2]), "+f"(d[3])
        : "r"(a[0]), "r"(a[1]), "r"(a[2]), "r"(a[3]), "r"(b[0]), "r"(b[1]));
}

// ---------------- tensor-core GEMM: Out[m, pix] = W[m,:] @ X[:, pix] ----------------
// EPI: 0 = (+bias if given); 1 = gelu(+bias); 2 = +bias + residual
constexpr int KC = 64;        // k-chunk
constexpr int SA = 72;        // A smem stride (bf16 elems), conflict-free for ldmatrix
constexpr int SB = 136;       // B smem stride
constexpr int A_BYTES = 128 * SA * 2;   // 18432
constexpr int B_BYTES = KC * SB * 2;    // 17408
constexpr int GSMEM = 2 * A_BYTES + 2 * B_BYTES;  // 71680

template <int KTOT, int MTOT, int EPI, bool SPLIT>
__global__ __launch_bounds__(256) void gemm_mma(
    const float* __restrict__ X0, const float* __restrict__ X1,
    const float* __restrict__ W,  const float* __restrict__ Bias,
    const float* __restrict__ Res, float* __restrict__ Out)
{
    extern __shared__ __align__(16) char sm[];
    char* Ah = sm;
    char* Al = sm + A_BYTES;
    char* Bh = sm + 2 * A_BYTES;
    char* Bl = sm + 2 * A_BYTES + B_BYTES;
    const uint32_t ah_sm = smem_u32(Ah), al_sm = smem_u32(Al);
    const uint32_t bh_sm = smem_u32(Bh), bl_sm = smem_u32(Bl);

    const int img = blockIdx.z;
    const int p0  = blockIdx.x * 128;
    const int m0  = blockIdx.y * 128;
    const int tid = threadIdx.x;
    const int lane = tid & 31, wid = tid >> 5;
    const int wm = wid >> 2, wn = wid & 3;        // 2 x 4 warp grid

    float acc[4][4][4];
#pragma unroll
    for (int i = 0; i < 4; i++)
#pragma unroll
        for (int j = 0; j < 4; j++)
#pragma unroll
            for (int q = 0; q < 4; q++) acc[i][j][q] = 0.f;

    constexpr int NCH  = KTOT / KC;
    constexpr int KCHX = SPLIT ? 128 : KTOT;

    // ldmatrix per-thread address components
    const int lr  = lane & 7;           // row within 8x8 tile
    const int lth = (lane >> 3) & 1;    // +8 rows (tile pair)
    const int ltv = lane >> 4;          // +8 cols (16 bytes)
    const uint32_t a_row = (uint32_t)(wm * 64 + lth * 8 + lr);

#pragma unroll 1
    for (int c = 0; c < NCH; c++) {
        __syncthreads();   // previous chunk's mma reads done
        const float* Xc = (SPLIT && c >= 2) ? X1 : X0;
        const int kbase = SPLIT ? (c & 1) * KC : c * KC;

        // A chunk: 128 m-rows x 32 k-pairs
#pragma unroll 4
        for (int it = 0; it < 16; it++) {
            int idx = tid + it * 256;
            int kp = idx & 31, m = idx >> 5;
            const float2 wv = *reinterpret_cast<const float2*>(
                &W[(size_t)(m0 + m) * KTOT + c * KC + 2 * kp]);
            uint32_t hi, lo;
            split_pack(wv.x, wv.y, hi, lo);
            *reinterpret_cast<uint32_t*>(Ah + m * (SA * 2) + kp * 4) = hi;
            *reinterpret_cast<uint32_t*>(Al + m * (SA * 2) + kp * 4) = lo;
        }
        // B chunk: 64 k-rows x 64 pix-pairs
#pragma unroll 4
        for (int it = 0; it < 16; it++) {
            int idx = tid + it * 256;
            int np = idx & 63, kr = idx >> 6;
            const float2 xv = *reinterpret_cast<const float2*>(
                &Xc[((size_t)img * KCHX + kbase + kr) * NPIX + p0 + 2 * np]);
            uint32_t hi, lo;
            split_pack(xv.x, xv.y, hi, lo);
            *reinterpret_cast<uint32_t*>(Bh + kr * (SB * 2) + np * 4) = hi;
            *reinterpret_cast<uint32_t*>(Bl + kr * (SB * 2) + np * 4) = lo;
        }
        __syncthreads();

#pragma unroll
        for (int kk = 0; kk < KC / 16; kk++) {
            uint32_t af[4][4];
            uint32_t bfh[4][2], bfl[4][2];
            const uint32_t a_off = ((a_row) * SA + kk * 16) * 2 + ltv * 16;
            const uint32_t b_off = ((uint32_t)(kk * 16 + lth * 8 + lr) * SB) * 2
                                   + (wn * 32) * 2 + ltv * 16;
            // A hi frags (4 m-frags)
#pragma unroll
            for (int mf = 0; mf < 4; mf++)
                ldm_x4(af[mf], ah_sm + a_off + mf * 16 * SA * 2);
            // B hi frags (4 n-frags via 2 x4.trans)
#pragma unroll
            for (int nh = 0; nh < 2; nh++) {
                uint32_t r[4];
                ldm_x4t(r, bh_sm + b_off + nh * 32);
                bfh[nh * 2][0] = r[0]; bfh[nh * 2][1] = r[1];
                bfh[nh * 2 + 1][0] = r[2]; bfh[nh * 2 + 1][1] = r[3];
            }
            // pass 1: hi * hi
#pragma unroll
            for (int mf = 0; mf < 4; mf++)
#pragma unroll
                for (int nf = 0; nf < 4; nf++)
                    mma_bf16(acc[mf][nf], af[mf], bfh[nf]);
            // B lo frags
#pragma unroll
            for (int nh = 0; nh < 2; nh++) {
                uint32_t r[4];
                ldm_x4t(r, bl_sm + b_off + nh * 32);
                bfl[nh * 2][0] = r[0]; bfl[nh * 2][1] = r[1];
                bfl[nh * 2 + 1][0] = r[2]; bfl[nh * 2 + 1][1] = r[3];
            }
            // pass 2: hi * lo
#pragma unroll
            for (int mf = 0; mf < 4; mf++)
#pragma unroll
                for (int nf = 0; nf < 4; nf++)
                    mma_bf16(acc[mf][nf], af[mf], bfl[nf]);
            // A lo frags (overwrite af)
#pragma unroll
            for (int mf = 0; mf < 4; mf++)
                ldm_x4(af[mf], al_sm + a_off + mf * 16 * SA * 2);
            // pass 3: lo * hi
#pragma unroll
            for (int mf = 0; mf < 4; mf++)
#pragma unroll
                for (int nf = 0; nf < 4; nf++)
                    mma_bf16(acc[mf][nf], af[mf], bfh[nf]);
        }
    }

    // epilogue
    const int g = lane >> 2, tg = lane & 3;
#pragma unroll
    for (int mf = 0; mf < 4; mf++) {
#pragma unroll
        for (int half = 0; half < 2; half++) {
            const int m = m0 + wm * 64 + mf * 16 + half * 8 + g;
            const float bias = Bias ? Bias[m] : 0.f;
            const size_t rowb = ((size_t)img * MTOT + m) * NPIX;
            const float* resrow = (EPI == 2) ? &Res[((size_t)img * CDIM + m) * NPIX] : nullptr;
#pragma unroll
            for (int nf = 0; nf < 4; nf++) {
                const int px = p0 + wn * 32 + nf * 8 + 2 * tg;
                float v0 = acc[mf][nf][half * 2 + 0] + bias;
                float v1 = acc[mf][nf][half * 2 + 1] + bias;
                if (EPI == 1) { v0 = gelu_exact(v0); v1 = gelu_exact(v1); }
                if (EPI == 2) { v0 += resrow[px]; v1 += resrow[px + 1]; }
                *reinterpret_cast<float2*>(&Out[rowb + px]) = make_float2(v0, v1);
            }
        }
    }
}

// ---------------- depthwise 3x3 + bias + GELU ----------------
__global__ __launch_bounds__(256) void dw3x3(
    const float* __restrict__ in, const float* __restrict__ wd,
    const float* __restrict__ bd, float* __restrict__ out)
{
    int c = blockIdx.y, img = blockIdx.z;
    int pix = blockIdx.x * 256 + threadIdx.x;
    int h = pix >> 7, w = pix & 127;
    const float* p = in + ((size_t)img * CDIM + c) * NPIX;
    float s = bd[c];
#pragma unroll
    for (int ky = 0; ky < 3; ky++) {
        int hh = h + ky - 1;
        if ((unsigned)hh >= 128u) continue;
#pragma unroll
        for (int kx = 0; kx < 3; kx++) {
            int ww = w + kx - 1;
            if ((unsigned)ww >= 128u) continue;
            s = fmaf(wd[c * 9 + ky * 3 + kx], p[hh * WW + ww], s);
        }
    }
    out[((size_t)img * CDIM + c) * NPIX + pix] = gelu_exact(s);
}

// ---------------- minGRU scan over V ----------------
__global__ __launch_bounds__(256) void gru_scan(const float* __restrict__ hg, float* __restrict__ g)
{
    int c = blockIdx.y, b = blockIdx.z;
    int pix = blockIdx.x * 256 + threadIdx.x;
    float h = 0.f;
#pragma unroll
    for (int v = 0; v < NV; v++) {
        size_t base = (((size_t)(b * NV + v)) * 2 * CDIM + c) * NPIX + pix;
        float hid = hg[base];
        float gt  = hg[base + (size_t)CDIM * NPIX];
        float z  = 1.f / (1.f + expf(-gt));
        float ht = (hid >= 0.f) ? (hid + 0.5f) : (1.f / (1.f + expf(-hid)));
        h = (1.f - z) * h + z * ht;
        g[(((size_t)(b * NV + v)) * CDIM + c) * NPIX + pix] = h;
    }
}

// ---------------- alpha: 3x3 conv C->1 ----------------
__global__ __launch_bounds__(256) void alpha_conv(
    const float* __restrict__ g2, const float* __restrict__ aw,
    const float* __restrict__ ab, float* __restrict__ alpha)
{
    __shared__ float w[1152];
    for (int i = threadIdx.x; i < 1152; i += 256) w[i] = aw[i];
    __syncthreads();
    int img = blockIdx.z;
    int pix = blockIdx.x * 256 + threadIdx.x;
    int h = pix >> 7, x = pix & 127;
    float s = ab[0];
    const float* base = g2 + (size_t)img * CDIM * NPIX;
    for (int c = 0; c < CDIM; c++) {
        const float* p  = base + (size_t)c * NPIX;
        const float* wc = w + c * 9;
#pragma unroll
        for (int ky = 0; ky < 3; ky++) {
            int hh = h + ky - 1;
            if ((unsigned)hh >= 128u) continue;
#pragma unroll
            for (int kx = 0; kx < 3; kx++) {
                int ww = x + kx - 1;
                if ((unsigned)ww >= 128u) continue;
                s = fmaf(wc[ky * 3 + kx], p[hh * WW + ww], s);
            }
        }
    }
    alpha[(size_t)img * NPIX + pix] = s;
}

// ---------------- softmax over V + weighted pool ----------------
__global__ __launch_bounds__(256) void pool_k(
    const float* __restrict__ g2, const float* __restrict__ alpha, float* __restrict__ out)
{
    int b = blockIdx.z;
    int pix = blockIdx.x * 256 + threadIdx.x;
    float a[NV];
    float mx = -1e30f;
#pragma unroll
    for (int v = 0; v < NV; v++) {
        a[v] = alpha[(size_t)(b * NV + v) * NPIX + pix];
        mx = fmaxf(mx, a[v]);
    }
    float sum = 0.f;
#pragma unroll
    for (int v = 0; v < NV; v++) { a[v] = expf(a[v] - mx); sum += a[v]; }
    float inv = 1.f / sum;
#pragma unroll
    for (int v = 0; v < NV; v++) a[v] *= inv;
    for (int c = 0; c < CDIM; c++) {
        float s = 0.f;
#pragma unroll
        for (int v = 0; v < NV; v++)
            s = fmaf(a[v], g2[(((size_t)(b * NV + v)) * CDIM + c) * NPIX + pix], s);
        out[((size_t)b * CDIM + c) * NPIX + pix] = s;
    }
}

// ---------------- pixel-shuffle(4) + 3x3 conv 8->3 (512->512 resize = identity) ----------------
__global__ __launch_bounds__(256) void outc_k(
    const float* __restrict__ u, const float* __restrict__ wt,
    const float* __restrict__ bs, float* __restrict__ out)
{
    __shared__ float w[216];
    if (threadIdx.x < 216) w[threadIdx.x] = wt[threadIdx.x];
    __syncthreads();
    int b = blockIdx.z, co = blockIdx.y;
    int idx = blockIdx.x * 256 + threadIdx.x;
    int y = idx >> 9, x = idx & 511;
    float s = bs[co];
    const float* ub = u + (size_t)b * CDIM * NPIX;
#pragma unroll
    for (int ky = 0; ky < 3; ky++) {
        int yy = y + ky - 1;
        if ((unsigned)yy >= 512u) continue;
        int sy = yy & 3, hy = yy >> 2;
#pragma unroll
        for (int kx = 0; kx < 3; kx++) {
            int xx = x + kx - 1;
            if ((unsigned)xx >= 512u) continue;
            int sx = xx & 3, hx = xx >> 2;
            const float* up = ub + (size_t)(sy * 4 + sx) * NPIX + hy * WW + hx;
#pragma unroll
            for (int ci = 0; ci < 8; ci++)
                s = fmaf(w[(co * 8 + ci) * 9 + ky * 3 + kx], up[(size_t)ci * 16 * NPIX], s);
        }
    }
    out[((size_t)b * 3 + co) * (512 * 512) + idx] = s;
}

// ---------------- launch ----------------
extern "C" void kernel_launch(void* const* d_in, const int* in_sizes, int n_in,
                              void* d_out, int out_size)
{
    const float* feats     = (const float*)d_in[0];
    const float* prj       = (const float*)d_in[1];
    const float* merge_w1  = (const float*)d_in[2];
    const float* merge_b1  = (const float*)d_in[3];
    const float* merge_wd  = (const float*)d_in[4];
    const float* merge_bd  = (const float*)d_in[5];
    const float* merge_w2  = (const float*)d_in[6];
    const float* merge_b2  = (const float*)d_in[7];
    const float* gru_w     = (const float*)d_in[8];
    const float* gru_bw    = (const float*)d_in[9];
    const float* alpha_w   = (const float*)d_in[10];
    const float* alpha_b   = (const float*)d_in[11];
    const float* up_w      = (const float*)d_in[12];
    const float* up_b      = (const float*)d_in[13];
    const float* outc_w    = (const float*)d_in[14];
    const float* outc_b    = (const float*)d_in[15];

    float *bufA, *bufB, *bufC, *hg, *alp, *pool, *u;
    cudaGetSymbolAddress((void**)&bufA, g_bufA);
    cudaGetSymbolAddress((void**)&bufB, g_bufB);
    cudaGetSymbolAddress((void**)&bufC, g_bufC);
    cudaGetSymbolAddress((void**)&hg,   g_hg);
    cudaGetSymbolAddress((void**)&alp,  g_alp);
    cudaGetSymbolAddress((void**)&pool, g_pool);
    cudaGetSymbolAddress((void**)&u,    g_u);

    cudaFuncSetAttribute(gemm_mma<256, 128, 1, true >, cudaFuncAttributeMaxDynamicSharedMemorySize, GSMEM);
    cudaFuncSetAttribute(gemm_mma<128, 128, 2, false>, cudaFuncAttributeMaxDynamicSharedMemorySize, GSMEM);
    cudaFuncSetAttribute(gemm_mma<128, 256, 0, false>, cudaFuncAttributeMaxDynamicSharedMemorySize, GSMEM);
    cudaFuncSetAttribute(gemm_mma<128, 128, 0, false>, cudaFuncAttributeMaxDynamicSharedMemorySize, GSMEM);

    // merge: 1x1 (2C->C) + GELU
    gemm_mma<256, 128, 1, true ><<<dim3(128, 1, BVI), 256, GSMEM>>>(feats, prj, merge_w1, merge_b1, nullptr, bufA);
    // depthwise 3x3 + GELU
    dw3x3<<<dim3(64, CDIM, BVI), 256>>>(bufA, merge_wd, merge_bd, bufB);
    // 1x1 (C->C) + bias + residual
    gemm_mma<128, 128, 2, false><<<dim3(128, 1, BVI), 256, GSMEM>>>(bufB, nullptr, merge_w2, merge_b2, feats, bufC);
    // fwd GRU linear (C -> 2C)
    gemm_mma<128, 256, 0, false><<<dim3(128, 2, BVI), 256, GSMEM>>>(bufC, nullptr, gru_w, nullptr, nullptr, hg);
    gru_scan<<<dim3(64, CDIM, NB), 256>>>(hg, bufA);
    // bwd GRU linear (H-flips cancel -> forward scan)
    gemm_mma<128, 256, 0, false><<<dim3(128, 2, BVI), 256, GSMEM>>>(bufA, nullptr, gru_bw, nullptr, nullptr, hg);
    gru_scan<<<dim3(64, CDIM, NB), 256>>>(hg, bufB);
    // alpha conv + softmax pool
    alpha_conv<<<dim3(64, 1, BVI), 256>>>(bufB, alpha_w, alpha_b, alp);
    pool_k<<<dim3(64, 1, NB), 256>>>(bufB, alp, pool);
    // up 1x1 conv
    gemm_mma<128, 128, 0, false><<<dim3(128, 1, NB), 256, GSMEM>>>(pool, nullptr, up_w, up_b, nullptr, u);
    // pixel shuffle + outc 3x3
    outc_k<<<dim3(1024, 3, NB), 256>>>(u, outc_w, outc_b, (float*)d_out);
}

// round 5
// speedup vs baseline: 2.1779x; 1.2071x over previous
#include <cuda_runtime.h>
#include <cuda_bf16.h>
#include <math.h>
#include <stdint.h>

#define HH 128
#define WW 128
#define NPIX 16384
#define CDIM 128
#define NB 2
#define NV 6
#define BVI 12

// ---------------- scratch ----------------
__device__ float g_bufA[(size_t)BVI * CDIM * NPIX];
__device__ float g_bufB[(size_t)BVI * CDIM * NPIX];
__device__ float g_bufC[(size_t)BVI * CDIM * NPIX];
__device__ float g_hg  [(size_t)BVI * 2 * CDIM * NPIX];
__device__ float g_alp [(size_t)BVI * NPIX];
__device__ float g_pool[(size_t)NB * CDIM * NPIX];
__device__ float g_u   [(size_t)NB * CDIM * NPIX];

__device__ __forceinline__ float gelu_exact(float x) {
    return 0.5f * x * (1.0f + erff(x * 0.70710678118654752f));
}

__device__ __forceinline__ uint32_t smem_u32(const void* p) {
    return (uint32_t)__cvta_generic_to_shared(p);
}

// fp32 pair -> bf16x2 hi + bf16x2 lo(residual); lo halfword = first element
__device__ __forceinline__ void split_pack(float v0, float v1, uint32_t& hi, uint32_t& lo) {
    asm("cvt.rn.bf16x2.f32 %0, %1, %2;" : "=r"(hi) : "f"(v1), "f"(v0));
    float r0 = v0 - __uint_as_float(hi << 16);
    float r1 = v1 - __uint_as_float(hi & 0xffff0000u);
    asm("cvt.rn.bf16x2.f32 %0, %1, %2;" : "=r"(lo) : "f"(r1), "f"(r0));
}

__device__ __forceinline__ void ldm_x4(uint32_t* r, uint32_t addr) {
    asm volatile("ldmatrix.sync.aligned.m8n8.x4.shared.b16 {%0,%1,%2,%3}, [%4];"
                 : "=r"(r[0]), "=r"(r[1]), "=r"(r[2]), "=r"(r[3]) : "r"(addr));
}
__device__ __forceinline__ void ldm_x4t(uint32_t* r, uint32_t addr) {
    asm volatile("ldmatrix.sync.aligned.m8n8.x4.trans.shared.b16 {%0,%1,%2,%3}, [%4];"
                 : "=r"(r[0]), "=r"(r[1]), "=r"(r[2]), "=r"(r[3]) : "r"(addr));
}
__device__ __forceinline__ void mma_bf16(float* d, const uint32_t* a, const uint32_t* b) {
    asm volatile(
        "mma.sync.aligned.m16n8k16.row.col.f32.bf16.bf16.f32 "
        "{%0,%1,%2,%3}, {%4,%5,%6,%7}, {%8,%9}, {%0,%1,%2,%3};"
        : "+f"(d[0]), "+f"(d[1]), "+f"(d[2]), "+f"(d[3])
        : "r"(a[0]), "r"(a[1]), "r"(a[2]), "r"(a[3]), "r"(b[0]), "r"(b[1]));
}

// ---------------- tensor-core GEMM: Out[m, pix] = W[m,:] @ X[:, pix] ----------------
// EPI: 0 = (+bias if given); 1 = gelu(+bias); 2 = +bias + residual
constexpr int KC = 64;        // k-chunk
constexpr int SA = 72;        // A smem stride (bf16 elems), conflict-free for ldmatrix
constexpr int SB = 136;       // B smem stride
constexpr int A_BYTES = 128 * SA * 2;   // 18432
constexpr int B_BYTES = KC * SB * 2;    // 17408
constexpr int GSMEM = 2 * A_BYTES + 2 * B_BYTES;  // 71680 (x2 CTAs = 143KB/SM)

template <int KTOT, int MTOT, int EPI, bool SPLIT>
__global__ __launch_bounds__(256, 2) void gemm_mma(
    const float* __restrict__ X0, const float* __restrict__ X1,
    const float* __restrict__ W,  const float* __restrict__ Bias,
    const float* __restrict__ Res, float* __restrict__ Out)
{
    extern __shared__ __align__(16) char sm[];
    char* Ah = sm;
    char* Al = sm + A_BYTES;
    char* Bh = sm + 2 * A_BYTES;
    char* Bl = sm + 2 * A_BYTES + B_BYTES;
    const uint32_t ah_sm = smem_u32(Ah), al_sm = smem_u32(Al);
    const uint32_t bh_sm = smem_u32(Bh), bl_sm = smem_u32(Bl);

    const int img = blockIdx.z;
    const int p0  = blockIdx.x * 128;
    const int m0  = blockIdx.y * 128;
    const int tid = threadIdx.x;
    const int lane = tid & 31, wid = tid >> 5;
    const int wm = wid >> 2, wn = wid & 3;        // 2 x 4 warp grid

    float acc[4][4][4];
#pragma unroll
    for (int i = 0; i < 4; i++)
#pragma unroll
        for (int j = 0; j < 4; j++)
#pragma unroll
            for (int q = 0; q < 4; q++) acc[i][j][q] = 0.f;

    constexpr int NCH  = KTOT / KC;
    constexpr int KCHX = SPLIT ? 128 : KTOT;

    // ldmatrix per-thread address components
    const int lr  = lane & 7;           // row within 8x8 tile
    const int lth = (lane >> 3) & 1;    // +8 rows (tile pair)
    const int ltv = lane >> 4;          // +8 cols (16 bytes)
    const uint32_t a_row = (uint32_t)(wm * 64 + lth * 8 + lr);

#pragma unroll 1
    for (int c = 0; c < NCH; c++) {
        __syncthreads();   // previous chunk's mma reads done
        const float* Xc = (SPLIT && c >= 2) ? X1 : X0;
        const int kbase = SPLIT ? (c & 1) * KC : c * KC;

        // A chunk: 128 m-rows x 32 k-pairs
#pragma unroll 4
        for (int it = 0; it < 16; it++) {
            int idx = tid + it * 256;
            int kp = idx & 31, m = idx >> 5;
            const float2 wv = *reinterpret_cast<const float2*>(
                &W[(size_t)(m0 + m) * KTOT + c * KC + 2 * kp]);
            uint32_t hi, lo;
            split_pack(wv.x, wv.y, hi, lo);
            *reinterpret_cast<uint32_t*>(Ah + m * (SA * 2) + kp * 4) = hi;
            *reinterpret_cast<uint32_t*>(Al + m * (SA * 2) + kp * 4) = lo;
        }
        // B chunk: 64 k-rows x 64 pix-pairs
#pragma unroll 4
        for (int it = 0; it < 16; it++) {
            int idx = tid + it * 256;
            int np = idx & 63, kr = idx >> 6;
            const float2 xv = *reinterpret_cast<const float2*>(
                &Xc[((size_t)img * KCHX + kbase + kr) * NPIX + p0 + 2 * np]);
            uint32_t hi, lo;
            split_pack(xv.x, xv.y, hi, lo);
            *reinterpret_cast<uint32_t*>(Bh + kr * (SB * 2) + np * 4) = hi;
            *reinterpret_cast<uint32_t*>(Bl + kr * (SB * 2) + np * 4) = lo;
        }
        __syncthreads();

#pragma unroll
        for (int kk = 0; kk < KC / 16; kk++) {
            uint32_t af[4][4];
            uint32_t bfh[4][2], bfl[4][2];
            const uint32_t a_off = ((a_row) * SA + kk * 16) * 2 + ltv * 16;
            const uint32_t b_off = ((uint32_t)(kk * 16 + lth * 8 + lr) * SB) * 2
                                   + (wn * 32) * 2 + ltv * 16;
            // A hi frags (4 m-frags)
#pragma unroll
            for (int mf = 0; mf < 4; mf++)
                ldm_x4(af[mf], ah_sm + a_off + mf * 16 * SA * 2);
            // B hi frags (4 n-frags via 2 x4.trans)
#pragma unroll
            for (int nh = 0; nh < 2; nh++) {
                uint32_t r[4];
                ldm_x4t(r, bh_sm + b_off + nh * 32);
                bfh[nh * 2][0] = r[0]; bfh[nh * 2][1] = r[1];
                bfh[nh * 2 + 1][0] = r[2]; bfh[nh * 2 + 1][1] = r[3];
            }
            // pass 1: hi * hi
#pragma unroll
            for (int mf = 0; mf < 4; mf++)
#pragma unroll
                for (int nf = 0; nf < 4; nf++)
                    mma_bf16(acc[mf][nf], af[mf], bfh[nf]);
            // B lo frags
#pragma unroll
            for (int nh = 0; nh < 2; nh++) {
                uint32_t r[4];
                ldm_x4t(r, bl_sm + b_off + nh * 32);
                bfl[nh * 2][0] = r[0]; bfl[nh * 2][1] = r[1];
                bfl[nh * 2 + 1][0] = r[2]; bfl[nh * 2 + 1][1] = r[3];
            }
            // pass 2: hi * lo
#pragma unroll
            for (int mf = 0; mf < 4; mf++)
#pragma unroll
                for (int nf = 0; nf < 4; nf++)
                    mma_bf16(acc[mf][nf], af[mf], bfl[nf]);
            // A lo frags (overwrite af)
#pragma unroll
            for (int mf = 0; mf < 4; mf++)
                ldm_x4(af[mf], al_sm + a_off + mf * 16 * SA * 2);
            // pass 3: lo * hi
#pragma unroll
            for (int mf = 0; mf < 4; mf++)
#pragma unroll
                for (int nf = 0; nf < 4; nf++)
                    mma_bf16(acc[mf][nf], af[mf], bfh[nf]);
        }
    }

    // epilogue
    const int g = lane >> 2, tg = lane & 3;
#pragma unroll
    for (int mf = 0; mf < 4; mf++) {
#pragma unroll
        for (int half = 0; half < 2; half++) {
            const int m = m0 + wm * 64 + mf * 16 + half * 8 + g;
            const float bias = Bias ? Bias[m] : 0.f;
            const size_t rowb = ((size_t)img * MTOT + m) * NPIX;
            const float* resrow = (EPI == 2) ? &Res[((size_t)img * CDIM + m) * NPIX] : nullptr;
#pragma unroll
            for (int nf = 0; nf < 4; nf++) {
                const int px = p0 + wn * 32 + nf * 8 + 2 * tg;
                float v0 = acc[mf][nf][half * 2 + 0] + bias;
                float v1 = acc[mf][nf][half * 2 + 1] + bias;
                if (EPI == 1) { v0 = gelu_exact(v0); v1 = gelu_exact(v1); }
                if (EPI == 2) { v0 += resrow[px]; v1 += resrow[px + 1]; }
                *reinterpret_cast<float2*>(&Out[rowb + px]) = make_float2(v0, v1);
            }
        }
    }
}

// ---------------- depthwise 3x3 + bias + GELU ----------------
__global__ __launch_bounds__(256) void dw3x3(
    const float* __restrict__ in, const float* __restrict__ wd,
    const float* __restrict__ bd, float* __restrict__ out)
{
    int c = blockIdx.y, img = blockIdx.z;
    int pix = blockIdx.x * 256 + threadIdx.x;
    int h = pix >> 7, w = pix & 127;
    const float* p = in + ((size_t)img * CDIM + c) * NPIX;
    float s = bd[c];
#pragma unroll
    for (int ky = 0; ky < 3; ky++) {
        int hh = h + ky - 1;
        if ((unsigned)hh >= 128u) continue;
#pragma unroll
        for (int kx = 0; kx < 3; kx++) {
            int ww = w + kx - 1;
            if ((unsigned)ww >= 128u) continue;
            s = fmaf(wd[c * 9 + ky * 3 + kx], p[hh * WW + ww], s);
        }
    }
    out[((size_t)img * CDIM + c) * NPIX + pix] = gelu_exact(s);
}

// ---------------- minGRU scan over V ----------------
__global__ __launch_bounds__(256) void gru_scan(const float* __restrict__ hg, float* __restrict__ g)
{
    int c = blockIdx.y, b = blockIdx.z;
    int pix = blockIdx.x * 256 + threadIdx.x;
    float h = 0.f;
#pragma unroll
    for (int v = 0; v < NV; v++) {
        size_t base = (((size_t)(b * NV + v)) * 2 * CDIM + c) * NPIX + pix;
        float hid = hg[base];
        float gt  = hg[base + (size_t)CDIM * NPIX];
        float z  = 1.f / (1.f + expf(-gt));
        float ht = (hid >= 0.f) ? (hid + 0.5f) : (1.f / (1.f + expf(-hid)));
        h = (1.f - z) * h + z * ht;
        g[(((size_t)(b * NV + v)) * CDIM + c) * NPIX + pix] = h;
    }
}

// ---------------- alpha: 3x3 conv C->1 ----------------
__global__ __launch_bounds__(256) void alpha_conv(
    const float* __restrict__ g2, const float* __restrict__ aw,
    const float* __restrict__ ab, float* __restrict__ alpha)
{
    __shared__ float w[1152];
    for (int i = threadIdx.x; i < 1152; i += 256) w[i] = aw[i];
    __syncthreads();
    int img = blockIdx.z;
    int pix = blockIdx.x * 256 + threadIdx.x;
    int h = pix >> 7, x = pix & 127;
    float s = ab[0];
    const float* base = g2 + (size_t)img * CDIM * NPIX;
    for (int c = 0; c < CDIM; c++) {
        const float* p  = base + (size_t)c * NPIX;
        const float* wc = w + c * 9;
#pragma unroll
        for (int ky = 0; ky < 3; ky++) {
            int hh = h + ky - 1;
            if ((unsigned)hh >= 128u) continue;
#pragma unroll
            for (int kx = 0; kx < 3; kx++) {
                int ww = x + kx - 1;
                if ((unsigned)ww >= 128u) continue;
                s = fmaf(wc[ky * 3 + kx], p[hh * WW + ww], s);
            }
        }
    }
    alpha[(size_t)img * NPIX + pix] = s;
}

// ---------------- softmax over V + weighted pool ----------------
__global__ __launch_bounds__(256) void pool_k(
    const float* __restrict__ g2, const float* __restrict__ alpha, float* __restrict__ out)
{
    int b = blockIdx.z;
    int pix = blockIdx.x * 256 + threadIdx.x;
    float a[NV];
    float mx = -1e30f;
#pragma unroll
    for (int v = 0; v < NV; v++) {
        a[v] = alpha[(size_t)(b * NV + v) * NPIX + pix];
        mx = fmaxf(mx, a[v]);
    }
    float sum = 0.f;
#pragma unroll
    for (int v = 0; v < NV; v++) { a[v] = expf(a[v] - mx); sum += a[v]; }
    float inv = 1.f / sum;
#pragma unroll
    for (int v = 0; v < NV; v++) a[v] *= inv;
    for (int c = 0; c < CDIM; c++) {
        float s = 0.f;
#pragma unroll
        for (int v = 0; v < NV; v++)
            s = fmaf(a[v], g2[(((size_t)(b * NV + v)) * CDIM + c) * NPIX + pix], s);
        out[((size_t)b * CDIM + c) * NPIX + pix] = s;
    }
}

// ---------------- pixel-shuffle(4) + 3x3 conv 8->3 (512->512 resize = identity) ----------------
__global__ __launch_bounds__(256) void outc_k(
    const float* __restrict__ u, const float* __restrict__ wt,
    const float* __restrict__ bs, float* __restrict__ out)
{
    __shared__ float w[216];
    if (threadIdx.x < 216) w[threadIdx.x] = wt[threadIdx.x];
    __syncthreads();
    int b = blockIdx.z, co = blockIdx.y;
    int idx = blockIdx.x * 256 + threadIdx.x;
    int y = idx >> 9, x = idx & 511;
    float s = bs[co];
    const float* ub = u + (size_t)b * CDIM * NPIX;
#pragma unroll
    for (int ky = 0; ky < 3; ky++) {
        int yy = y + ky - 1;
        if ((unsigned)yy >= 512u) continue;
        int sy = yy & 3, hy = yy >> 2;
#pragma unroll
        for (int kx = 0; kx < 3; kx++) {
            int xx = x + kx - 1;
            if ((unsigned)xx >= 512u) continue;
            int sx = xx & 3, hx = xx >> 2;
            const float* up = ub + (size_t)(sy * 4 + sx) * NPIX + hy * WW + hx;
#pragma unroll
            for (int ci = 0; ci < 8; ci++)
                s = fmaf(w[(co * 8 + ci) * 9 + ky * 3 + kx], up[(size_t)ci * 16 * NPIX], s);
        }
    }
    out[((size_t)b * 3 + co) * (512 * 512) + idx] = s;
}

// ---------------- launch ----------------
extern "C" void kernel_launch(void* const* d_in, const int* in_sizes, int n_in,
                              void* d_out, int out_size)
{
    const float* feats     = (const float*)d_in[0];
    const float* prj       = (const float*)d_in[1];
    const float* merge_w1  = (const float*)d_in[2];
    const float* merge_b1  = (const float*)d_in[3];
    const float* merge_wd  = (const float*)d_in[4];
    const float* merge_bd  = (const float*)d_in[5];
    const float* merge_w2  = (const float*)d_in[6];
    const float* merge_b2  = (const float*)d_in[7];
    const float* gru_w     = (const float*)d_in[8];
    const float* gru_bw    = (const float*)d_in[9];
    const float* alpha_w   = (const float*)d_in[10];
    const float* alpha_b   = (const float*)d_in[11];
    const float* up_w      = (const float*)d_in[12];
    const float* up_b      = (const float*)d_in[13];
    const float* outc_w    = (const float*)d_in[14];
    const float* outc_b    = (const float*)d_in[15];

    float *bufA, *bufB, *bufC, *hg, *alp, *pool, *u;
    cudaGetSymbolAddress((void**)&bufA, g_bufA);
    cudaGetSymbolAddress((void**)&bufB, g_bufB);
    cudaGetSymbolAddress((void**)&bufC, g_bufC);
    cudaGetSymbolAddress((void**)&hg,   g_hg);
    cudaGetSymbolAddress((void**)&alp,  g_alp);
    cudaGetSymbolAddress((void**)&pool, g_pool);
    cudaGetSymbolAddress((void**)&u,    g_u);

    cudaFuncSetAttribute(gemm_mma<256, 128, 1, true >, cudaFuncAttributeMaxDynamicSharedMemorySize, GSMEM);
    cudaFuncSetAttribute(gemm_mma<128, 128, 2, false>, cudaFuncAttributeMaxDynamicSharedMemorySize, GSMEM);
    cudaFuncSetAttribute(gemm_mma<128, 256, 0, false>, cudaFuncAttributeMaxDynamicSharedMemorySize, GSMEM);
    cudaFuncSetAttribute(gemm_mma<128, 128, 0, false>, cudaFuncAttributeMaxDynamicSharedMemorySize, GSMEM);
    cudaFuncSetAttribute(gemm_mma<256, 128, 1, true >, cudaFuncAttributePreferredSharedMemoryCarveout, 100);
    cudaFuncSetAttribute(gemm_mma<128, 128, 2, false>, cudaFuncAttributePreferredSharedMemoryCarveout, 100);
    cudaFuncSetAttribute(gemm_mma<128, 256, 0, false>, cudaFuncAttributePreferredSharedMemoryCarveout, 100);
    cudaFuncSetAttribute(gemm_mma<128, 128, 0, false>, cudaFuncAttributePreferredSharedMemoryCarveout, 100);

    // merge: 1x1 (2C->C) + GELU
    gemm_mma<256, 128, 1, true ><<<dim3(128, 1, BVI), 256, GSMEM>>>(feats, prj, merge_w1, merge_b1, nullptr, bufA);
    // depthwise 3x3 + GELU
    dw3x3<<<dim3(64, CDIM, BVI), 256>>>(bufA, merge_wd, merge_bd, bufB);
    // 1x1 (C->C) + bias + residual
    gemm_mma<128, 128, 2, false><<<dim3(128, 1, BVI), 256, GSMEM>>>(bufB, nullptr, merge_w2, merge_b2, feats, bufC);
    // fwd GRU linear (C -> 2C)
    gemm_mma<128, 256, 0, false><<<dim3(128, 2, BVI), 256, GSMEM>>>(bufC, nullptr, gru_w, nullptr, nullptr, hg);
    gru_scan<<<dim3(64, CDIM, NB), 256>>>(hg, bufA);
    // bwd GRU linear (H-flips cancel -> forward scan)
    gemm_mma<128, 256, 0, false><<<dim3(128, 2, BVI), 256, GSMEM>>>(bufA, nullptr, gru_bw, nullptr, nullptr, hg);
    gru_scan<<<dim3(64, CDIM, NB), 256>>>(hg, bufB);
    // alpha conv + softmax pool
    alpha_conv<<<dim3(64, 1, BVI), 256>>>(bufB, alpha_w, alpha_b, alp);
    pool_k<<<dim3(64, 1, NB), 256>>>(bufB, alp, pool);
    // up 1x1 conv
    gemm_mma<128, 128, 0, false><<<dim3(128, 1, NB), 256, GSMEM>>>(pool, nullptr, up_w, up_b, nullptr, u);
    // pixel shuffle + outc 3x3
    outc_k<<<dim3(1024, 3, NB), 256>>>(u, outc_w, outc_b, (float*)d_out);
}